// round 11
// baseline (speedup 1.0000x reference)
#include <cuda_runtime.h>
#include <cuda_bf16.h>

#define NN 100000
#define EE 1250000
#define HH 64
#define GG 128
#define CC 10
#define NB 98           // ceil(NN/1024) scan blocks

// Scratch (device globals; only dereferenced from device code)
__device__ int   g_is64;             // 1 if edge_index/batch arrive as int64
__device__ int   g_degi[NN];
__device__ float g_dinv[NN];
__device__ int   g_rowptr[NN + 1];
__device__ int   g_cursor[NN];
__device__ int   g_blksum[NB];
__device__ int   g_csr_src[EE];
__device__ float g_bufA[NN * HH];   // dinv[row] * (h @ W)  (pre-scaled gather source)
__device__ float g_bufB[NN * HH];   // layer output / next input

__device__ __forceinline__ int load_idx(const void* p, long long i, int is64) {
    if (is64) return (int)((const long long*)p)[i];
    return ((const int*)p)[i];
}

// ---------------------------------------------------------------------------
// setup: zero degree histogram; block 0 additionally runs the dtype detector
// (int64 viewed as int32 has zero high words at odd positions).
// ---------------------------------------------------------------------------
__global__ void k_setup(const void* ei_raw) {
    int i = blockIdx.x * blockDim.x + threadIdx.x;
    if (i < NN) g_degi[i] = 0;
    if (blockIdx.x == 0) {
        __shared__ int cnt;
        if (threadIdx.x == 0) cnt = 0;
        __syncthreads();
        const int* p = (const int*)ei_raw;
        int z = 0;
        for (int k = threadIdx.x; k < 4096; k += 256)
            if (p[2 * k + 1] == 0) z++;
        atomicAdd(&cnt, z);
        __syncthreads();
        if (threadIdx.x == 0) g_is64 = (cnt > 2048) ? 1 : 0;
    }
}

__global__ void k_hist(const void* __restrict__ ei) {
    int e = blockIdx.x * blockDim.x + threadIdx.x;
    if (e < EE) {
        int d = load_idx(ei, (long long)EE + e, g_is64);
        atomicAdd(&g_degi[d], 1);
    }
}

// scan over degrees (exclusive, per 1024-block) + fused dinv computation
__global__ void k_scan1() {
    __shared__ int sh[1024];
    int t = threadIdx.x;
    int i = blockIdx.x * 1024 + t;
    int v = (i < NN) ? g_degi[i] : 0;
    if (i < NN) g_dinv[i] = rsqrtf(1.0f + (float)v);   // +1 self-loop
    sh[t] = v;
    __syncthreads();
    #pragma unroll
    for (int off = 1; off < 1024; off <<= 1) {
        int add = (t >= off) ? sh[t - off] : 0;
        __syncthreads();
        sh[t] += add;
        __syncthreads();
    }
    if (i < NN) g_rowptr[i] = sh[t] - v;          // exclusive
    if (t == 1023) g_blksum[blockIdx.x] = sh[t];
}

// parallel scan of the NB block sums
__global__ void k_scan2() {
    __shared__ int warp_tot[4];
    int t = threadIdx.x;            // 128 threads, NB=98 <= 128
    int lane = t & 31, w = t >> 5;
    int v = (t < NB) ? g_blksum[t] : 0;
    int s = v;
    #pragma unroll
    for (int off = 1; off < 32; off <<= 1) {
        int u = __shfl_up_sync(0xffffffffu, s, off);
        if (lane >= off) s += u;
    }
    if (lane == 31) warp_tot[w] = s;
    __syncthreads();
    int carry = 0;
    #pragma unroll
    for (int j = 0; j < 4; j++)
        if (j < w) carry += warp_tot[j];
    int incl = s + carry;
    if (t < NB) g_blksum[t] = incl - v;           // exclusive
    if (t == NB - 1) g_rowptr[NN] = incl;         // == EE
}

__global__ void k_scan3() {
    int i = blockIdx.x * blockDim.x + threadIdx.x;
    if (i < NN) {
        int v = g_rowptr[i] + g_blksum[i >> 10];
        g_rowptr[i] = v;
        g_cursor[i] = v;
    }
}

// scatter src ids only (norms are factored into bufA pre-scaling + epilogue)
__global__ void k_scatter(const void* __restrict__ ei) {
    int e = blockIdx.x * blockDim.x + threadIdx.x;
    if (e >= EE) return;
    int is64 = g_is64;
    int s = load_idx(ei, e, is64);
    int d = load_idx(ei, (long long)EE + e, is64);
    int pos = atomicAdd(&g_cursor[d], 1);
    g_csr_src[pos] = s;
}

// ---------------------------------------------------------------------------
// GEMM: g_bufA = dinv[row] * (act(h) @ W).  256 thr/block, 64 rows/block.
// Thread (tx,ty) owns rows ty*4..+3 x cols tx*4..+3 (LDS.128 weight loads).
// dinv scaling folded into the register epilogue (free).
// ---------------------------------------------------------------------------
__global__ void k_gemm(const float* __restrict__ x_in, const float* __restrict__ W,
                       int use_bufB, int relu) {
    __shared__ float Ws[64 * 64];
    __shared__ float hs[64 * 65];
    int t = threadIdx.x;
    int base = blockIdx.x * 64;
    const float* __restrict__ h = use_bufB ? (const float*)g_bufB : x_in;

    #pragma unroll
    for (int i = t; i < 1024; i += 256)
        *(float4*)&Ws[i * 4] = *(const float4*)&W[i * 4];

    #pragma unroll
    for (int i = t; i < 1024; i += 256) {
        int r = i >> 4;
        int c4 = (i & 15) << 2;
        int row = base + r;
        float4 v = make_float4(0.f, 0.f, 0.f, 0.f);
        if (row < NN) v = *(const float4*)(h + (size_t)row * 64 + c4);
        if (relu) {
            v.x = fmaxf(v.x, 0.f); v.y = fmaxf(v.y, 0.f);
            v.z = fmaxf(v.z, 0.f); v.w = fmaxf(v.w, 0.f);
        }
        hs[r * 65 + c4 + 0] = v.x;
        hs[r * 65 + c4 + 1] = v.y;
        hs[r * 65 + c4 + 2] = v.z;
        hs[r * 65 + c4 + 3] = v.w;
    }
    __syncthreads();

    int tx = t & 15, ty = t >> 4;
    float acc[4][4] = {};
    #pragma unroll
    for (int k = 0; k < 64; k++) {
        float4 w = *(const float4*)&Ws[k * 64 + tx * 4];
        #pragma unroll
        for (int i = 0; i < 4; i++) {
            float a = hs[(ty * 4 + i) * 65 + k];
            acc[i][0] = fmaf(a, w.x, acc[i][0]);
            acc[i][1] = fmaf(a, w.y, acc[i][1]);
            acc[i][2] = fmaf(a, w.z, acc[i][2]);
            acc[i][3] = fmaf(a, w.w, acc[i][3]);
        }
    }
    #pragma unroll
    for (int i = 0; i < 4; i++) {
        int row = base + ty * 4 + i;
        if (row < NN) {
            float di = g_dinv[row];
            float4 o = make_float4(acc[i][0] * di, acc[i][1] * di,
                                   acc[i][2] * di, acc[i][3] * di);
            *(float4*)(g_bufA + (size_t)row * 64 + tx * 4) = o;
        }
    }
}

// ---------------------------------------------------------------------------
// Aggregation (atomic-free): one warp per dst node, round-5 loop structure.
//   bufB[n] = b + dinv[n] * (bufA[n] + sum_e bufA[src_e])
// bufA is pre-scaled by dinv[src], so inner loop needs only ONE shfl (src id)
// and plain adds — no per-edge norm load/shfl/multiply at all.
// ---------------------------------------------------------------------------
__global__ void k_agg(const float* __restrict__ b) {
    int warp = (blockIdx.x * blockDim.x + threadIdx.x) >> 5;
    if (warp >= NN) return;
    int lane = threadIdx.x & 31;
    int n = warp;

    int beg = g_rowptr[n];
    int end = g_rowptr[n + 1];
    float di = g_dinv[n];

    float2 acc = *(const float2*)(g_bufA + (size_t)n * 64 + 2 * lane);

    for (int base = beg; base < end; base += 32) {
        int e = base + lane;
        int src = 0;
        if (e < end) src = g_csr_src[e];
        int cnt = min(32, end - base);
        for (int j = 0; j < cnt; j++) {        // warp-uniform trip count
            int sj = __shfl_sync(0xffffffffu, src, j);
            float2 v = *(const float2*)(g_bufA + (size_t)sj * 64 + 2 * lane);
            acc.x += v.x;
            acc.y += v.y;
        }
    }

    float2 bb = *(const float2*)(b + 2 * lane);
    float2 o;
    o.x = fmaf(di, acc.x, bb.x);
    o.y = fmaf(di, acc.y, bb.y);
    *(float2*)(g_bufB + (size_t)n * 64 + 2 * lane) = o;
}

// ---------------------------------------------------------------------------
// Fused mean-pool + head (batch sorted -> binary search per graph).
// ---------------------------------------------------------------------------
__global__ void k_pool_head(const void* __restrict__ batch,
                            const float* __restrict__ Wl,
                            const float* __restrict__ bl,
                            float* __restrict__ out) {
    __shared__ float4 sh[16][16];
    __shared__ float pooled[64];
    int g = blockIdx.x;
    int t = threadIdx.x;
    int q = t & 15;
    int grp = t >> 4;
    int is64 = g_is64;

    int lo = 0, hi = NN;
    while (lo < hi) { int m = (lo + hi) >> 1; if (load_idx(batch, m, is64) < g) lo = m + 1; else hi = m; }
    int start = lo;
    lo = start; hi = NN;
    while (lo < hi) { int m = (lo + hi) >> 1; if (load_idx(batch, m, is64) < g + 1) lo = m + 1; else hi = m; }
    int end = lo;
    float inv = 1.0f / fmaxf((float)(end - start), 1.0f);

    float4 acc = make_float4(0.f, 0.f, 0.f, 0.f);
    for (int i = start + grp; i < end; i += 16) {
        float4 v = *(const float4*)(g_bufB + (size_t)i * 64 + 4 * q);
        acc.x += v.x; acc.y += v.y; acc.z += v.z; acc.w += v.w;
    }
    sh[grp][q] = acc;
    __syncthreads();

    if (t < 16) {
        float4 s = make_float4(0.f, 0.f, 0.f, 0.f);
        #pragma unroll
        for (int j = 0; j < 16; j++) {
            float4 v = sh[j][t];
            s.x += v.x; s.y += v.y; s.z += v.z; s.w += v.w;
        }
        pooled[4 * t + 0] = s.x * inv;
        pooled[4 * t + 1] = s.y * inv;
        pooled[4 * t + 2] = s.z * inv;
        pooled[4 * t + 3] = s.w * inv;
    }
    __syncthreads();

    if (t < CC) {
        float acc2 = bl[t];
        #pragma unroll
        for (int f = 0; f < HH; f++)
            acc2 = fmaf(pooled[f], Wl[f * CC + t], acc2);
        out[g * CC + t] = acc2;
    }
}

// ---------------------------------------------------------------------------
extern "C" void kernel_launch(void* const* d_in, const int* in_sizes, int n_in,
                              void* d_out, int out_size) {
    const float* x     = (const float*)d_in[0];
    const void*  ei    = d_in[1];
    const void*  batch = d_in[2];
    const float* W1    = (const float*)d_in[3];
    const float* b1    = (const float*)d_in[4];
    const float* W2    = (const float*)d_in[5];
    const float* b2    = (const float*)d_in[6];
    const float* W3    = (const float*)d_in[7];
    const float* b3    = (const float*)d_in[8];
    const float* Wl    = (const float*)d_in[9];
    const float* bl    = (const float*)d_in[10];
    float* out = (float*)d_out;

    const int T = 256;
    const int gN   = (NN + T - 1) / T;
    const int gE   = (EE + T - 1) / T;
    const int gRow = (NN + 63) / 64;
    const int gAgg = (NN * 32 + T - 1) / T;

    k_setup<<<gN, T>>>(ei);        // launch 0
    k_hist<<<gE, T>>>(ei);         // launch 1
    k_scan1<<<NB, 1024>>>();       // launch 2  (produces dinv)
    k_gemm<<<gRow, T>>>(x, W1, 0, 0); // launch 3 — ncu capture slot: profiles GEMM
    k_scan2<<<1, 128>>>();         // launch 4
    k_scan3<<<gN, T>>>();          // launch 5
    k_scatter<<<gE, T>>>(ei);      // launch 6

    k_agg<<<gAgg, T>>>(b1);
    k_gemm<<<gRow, T>>>(x, W2, 1, 1);
    k_agg<<<gAgg, T>>>(b2);
    k_gemm<<<gRow, T>>>(x, W3, 1, 1);
    k_agg<<<gAgg, T>>>(b3);

    k_pool_head<<<GG, T>>>(batch, Wl, bl, out);
}

// round 15
// speedup vs baseline: 1.2028x; 1.2028x over previous
#include <cuda_runtime.h>
#include <cuda_bf16.h>

#define NN 100000
#define EE 1250000
#define HH 64
#define GG 128
#define CC 10
#define NB 98           // ceil(NN/1024) scan blocks
#define GR 64           // rows per GEMM block

// Scratch (device globals; only dereferenced from device code)
__device__ int   g_is64;             // 1 if edge_index/batch arrive as int64
__device__ int   g_degi[NN];
__device__ float g_dinv[NN];
__device__ int   g_rowptr[NN + 1];
__device__ int   g_cursor[NN];
__device__ int   g_blksum[NB];
__device__ int   g_csr_src[EE];
__device__ float g_bufA[NN * HH];   // dinv[row] * (h @ W)  (pre-scaled gather source)
__device__ float g_bufB[NN * HH];   // layer output / next input

__device__ __forceinline__ int load_idx(const void* p, long long i, int is64) {
    if (is64) return (int)((const long long*)p)[i];
    return ((const int*)p)[i];
}

// ---------------------------------------------------------------------------
// setup: zero degree histogram; block 0 additionally runs the dtype detector
// ---------------------------------------------------------------------------
__global__ void k_setup(const void* ei_raw) {
    int i = blockIdx.x * blockDim.x + threadIdx.x;
    if (i < NN) g_degi[i] = 0;
    if (blockIdx.x == 0) {
        __shared__ int cnt;
        if (threadIdx.x == 0) cnt = 0;
        __syncthreads();
        const int* p = (const int*)ei_raw;
        int z = 0;
        for (int k = threadIdx.x; k < 4096; k += 256)
            if (p[2 * k + 1] == 0) z++;
        atomicAdd(&cnt, z);
        __syncthreads();
        if (threadIdx.x == 0) g_is64 = (cnt > 2048) ? 1 : 0;
    }
}

__global__ void k_hist(const void* __restrict__ ei) {
    int e = blockIdx.x * blockDim.x + threadIdx.x;
    if (e < EE) {
        int d = load_idx(ei, (long long)EE + e, g_is64);
        atomicAdd(&g_degi[d], 1);
    }
}

// scan over degrees (exclusive, per 1024-block) + fused dinv computation
__global__ void k_scan1() {
    __shared__ int sh[1024];
    int t = threadIdx.x;
    int i = blockIdx.x * 1024 + t;
    int v = (i < NN) ? g_degi[i] : 0;
    if (i < NN) g_dinv[i] = rsqrtf(1.0f + (float)v);   // +1 self-loop
    sh[t] = v;
    __syncthreads();
    #pragma unroll
    for (int off = 1; off < 1024; off <<= 1) {
        int add = (t >= off) ? sh[t - off] : 0;
        __syncthreads();
        sh[t] += add;
        __syncthreads();
    }
    if (i < NN) g_rowptr[i] = sh[t] - v;          // exclusive
    if (t == 1023) g_blksum[blockIdx.x] = sh[t];
}

// parallel scan of the NB block sums
__global__ void k_scan2() {
    __shared__ int warp_tot[4];
    int t = threadIdx.x;            // 128 threads, NB=98 <= 128
    int lane = t & 31, w = t >> 5;
    int v = (t < NB) ? g_blksum[t] : 0;
    int s = v;
    #pragma unroll
    for (int off = 1; off < 32; off <<= 1) {
        int u = __shfl_up_sync(0xffffffffu, s, off);
        if (lane >= off) s += u;
    }
    if (lane == 31) warp_tot[w] = s;
    __syncthreads();
    int carry = 0;
    #pragma unroll
    for (int j = 0; j < 4; j++)
        if (j < w) carry += warp_tot[j];
    int incl = s + carry;
    if (t < NB) g_blksum[t] = incl - v;           // exclusive
    if (t == NB - 1) g_rowptr[NN] = incl;         // == EE
}

__global__ void k_scan3() {
    int i = blockIdx.x * blockDim.x + threadIdx.x;
    if (i < NN) {
        int v = g_rowptr[i] + g_blksum[i >> 10];
        g_rowptr[i] = v;
        g_cursor[i] = v;
    }
}

// scatter src ids only (norms are factored into bufA pre-scaling + epilogue)
__global__ void k_scatter(const void* __restrict__ ei) {
    int e = blockIdx.x * blockDim.x + threadIdx.x;
    if (e >= EE) return;
    int is64 = g_is64;
    int s = load_idx(ei, e, is64);
    int d = load_idx(ei, (long long)EE + e, is64);
    int pos = atomicAdd(&g_cursor[d], 1);
    g_csr_src[pos] = s;
}

// ---------------------------------------------------------------------------
// GEMM: g_bufA = dinv[row] * (act(h) @ W).
// 128 threads/block, 64 rows/block, 4x8 register tile per thread:
//   ty = t>>3 (rows ty*4..+3), tx = t&7 (cols tx*8..+7, contiguous).
// Per k: 4 scalar a-loads (broadcast, conflict-free via 65-stride padding)
// + 2 LDS.128 w-loads for 32 FMAs -> LDS:FFMA = 6:32 (was 5:16).
// smem = 16384 (Ws) + 16640 (hs) = 33024 B — well under the 48KB cap.
// ---------------------------------------------------------------------------
__global__ void k_gemm(const float* __restrict__ x_in, const float* __restrict__ W,
                       int use_bufB, int relu) {
    __shared__ float Ws[64 * 64];       // [k][col], row-major copy of W
    __shared__ float hs[GR * 65];       // [row][k], padded stride
    int t = threadIdx.x;                // 128 threads
    int base = blockIdx.x * GR;
    const float* __restrict__ h = use_bufB ? (const float*)g_bufB : x_in;

    // W: 1024 float4 over 128 threads
    #pragma unroll
    for (int i = t; i < 1024; i += 128)
        *(float4*)&Ws[i * 4] = *(const float4*)&W[i * 4];

    // h: 64 rows x 16 float4 = 1024 float4 over 128 threads
    #pragma unroll
    for (int i = t; i < 1024; i += 128) {
        int r = i >> 4;                 // 16 float4 per row
        int c4 = (i & 15) << 2;
        int row = base + r;
        float4 v = make_float4(0.f, 0.f, 0.f, 0.f);
        if (row < NN) v = *(const float4*)(h + (size_t)row * 64 + c4);
        if (relu) {
            v.x = fmaxf(v.x, 0.f); v.y = fmaxf(v.y, 0.f);
            v.z = fmaxf(v.z, 0.f); v.w = fmaxf(v.w, 0.f);
        }
        hs[r * 65 + c4 + 0] = v.x;
        hs[r * 65 + c4 + 1] = v.y;
        hs[r * 65 + c4 + 2] = v.z;
        hs[r * 65 + c4 + 3] = v.w;
    }
    __syncthreads();

    int tx = t & 7;                     // col group (8 contiguous cols)
    int ty = t >> 3;                    // row group (4 rows)
    float acc[4][8] = {};
    #pragma unroll 4
    for (int k = 0; k < 64; k++) {
        float4 w0 = *(const float4*)&Ws[k * 64 + tx * 8];
        float4 w1 = *(const float4*)&Ws[k * 64 + tx * 8 + 4];
        float wr[8] = {w0.x, w0.y, w0.z, w0.w, w1.x, w1.y, w1.z, w1.w};
        float ar[4];
        #pragma unroll
        for (int i = 0; i < 4; i++)
            ar[i] = hs[(ty * 4 + i) * 65 + k];
        #pragma unroll
        for (int i = 0; i < 4; i++)
            #pragma unroll
            for (int j = 0; j < 8; j++)
                acc[i][j] = fmaf(ar[i], wr[j], acc[i][j]);
    }

    #pragma unroll
    for (int i = 0; i < 4; i++) {
        int row = base + ty * 4 + i;
        if (row < NN) {
            float di = g_dinv[row];
            float4 o0 = make_float4(acc[i][0] * di, acc[i][1] * di,
                                    acc[i][2] * di, acc[i][3] * di);
            float4 o1 = make_float4(acc[i][4] * di, acc[i][5] * di,
                                    acc[i][6] * di, acc[i][7] * di);
            *(float4*)(g_bufA + (size_t)row * 64 + tx * 8)     = o0;
            *(float4*)(g_bufA + (size_t)row * 64 + tx * 8 + 4) = o1;
        }
    }
}

// ---------------------------------------------------------------------------
// Aggregation (atomic-free): one warp per dst node, round-5 loop structure.
//   bufB[n] = b + dinv[n] * (bufA[n] + sum_e bufA[src_e])
// bufA pre-scaled by dinv[src] -> inner loop: ONE shfl + LDG.64 + 2 FADD.
// ---------------------------------------------------------------------------
__global__ void k_agg(const float* __restrict__ b) {
    int warp = (blockIdx.x * blockDim.x + threadIdx.x) >> 5;
    if (warp >= NN) return;
    int lane = threadIdx.x & 31;
    int n = warp;

    int beg = g_rowptr[n];
    int end = g_rowptr[n + 1];
    float di = g_dinv[n];

    float2 acc = *(const float2*)(g_bufA + (size_t)n * 64 + 2 * lane);

    for (int base = beg; base < end; base += 32) {
        int e = base + lane;
        int src = 0;
        if (e < end) src = g_csr_src[e];
        int cnt = min(32, end - base);
        for (int j = 0; j < cnt; j++) {        // warp-uniform trip count
            int sj = __shfl_sync(0xffffffffu, src, j);
            float2 v = *(const float2*)(g_bufA + (size_t)sj * 64 + 2 * lane);
            acc.x += v.x;
            acc.y += v.y;
        }
    }

    float2 bb = *(const float2*)(b + 2 * lane);
    float2 o;
    o.x = fmaf(di, acc.x, bb.x);
    o.y = fmaf(di, acc.y, bb.y);
    *(float2*)(g_bufB + (size_t)n * 64 + 2 * lane) = o;
}

// ---------------------------------------------------------------------------
// Fused mean-pool + head (batch sorted -> binary search per graph).
// ---------------------------------------------------------------------------
__global__ void k_pool_head(const void* __restrict__ batch,
                            const float* __restrict__ Wl,
                            const float* __restrict__ bl,
                            float* __restrict__ out) {
    __shared__ float4 sh[16][16];
    __shared__ float pooled[64];
    int g = blockIdx.x;
    int t = threadIdx.x;
    int q = t & 15;
    int grp = t >> 4;
    int is64 = g_is64;

    int lo = 0, hi = NN;
    while (lo < hi) { int m = (lo + hi) >> 1; if (load_idx(batch, m, is64) < g) lo = m + 1; else hi = m; }
    int start = lo;
    lo = start; hi = NN;
    while (lo < hi) { int m = (lo + hi) >> 1; if (load_idx(batch, m, is64) < g + 1) lo = m + 1; else hi = m; }
    int end = lo;
    float inv = 1.0f / fmaxf((float)(end - start), 1.0f);

    float4 acc = make_float4(0.f, 0.f, 0.f, 0.f);
    for (int i = start + grp; i < end; i += 16) {
        float4 v = *(const float4*)(g_bufB + (size_t)i * 64 + 4 * q);
        acc.x += v.x; acc.y += v.y; acc.z += v.z; acc.w += v.w;
    }
    sh[grp][q] = acc;
    __syncthreads();

    if (t < 16) {
        float4 s = make_float4(0.f, 0.f, 0.f, 0.f);
        #pragma unroll
        for (int j = 0; j < 16; j++) {
            float4 v = sh[j][t];
            s.x += v.x; s.y += v.y; s.z += v.z; s.w += v.w;
        }
        pooled[4 * t + 0] = s.x * inv;
        pooled[4 * t + 1] = s.y * inv;
        pooled[4 * t + 2] = s.z * inv;
        pooled[4 * t + 3] = s.w * inv;
    }
    __syncthreads();

    if (t < CC) {
        float acc2 = bl[t];
        #pragma unroll
        for (int f = 0; f < HH; f++)
            acc2 = fmaf(pooled[f], Wl[f * CC + t], acc2);
        out[g * CC + t] = acc2;
    }
}

// ---------------------------------------------------------------------------
extern "C" void kernel_launch(void* const* d_in, const int* in_sizes, int n_in,
                              void* d_out, int out_size) {
    const float* x     = (const float*)d_in[0];
    const void*  ei    = d_in[1];
    const void*  batch = d_in[2];
    const float* W1    = (const float*)d_in[3];
    const float* b1    = (const float*)d_in[4];
    const float* W2    = (const float*)d_in[5];
    const float* b2    = (const float*)d_in[6];
    const float* W3    = (const float*)d_in[7];
    const float* b3    = (const float*)d_in[8];
    const float* Wl    = (const float*)d_in[9];
    const float* bl    = (const float*)d_in[10];
    float* out = (float*)d_out;

    const int T = 256;
    const int gN   = (NN + T - 1) / T;
    const int gE   = (EE + T - 1) / T;
    const int gRow = (NN + GR - 1) / GR;
    const int gAgg = (NN * 32 + T - 1) / T;

    k_setup<<<gN, T>>>(ei);             // launch 0
    k_hist<<<gE, T>>>(ei);              // launch 1
    k_scan1<<<NB, 1024>>>();            // launch 2 (produces dinv)
    k_gemm<<<gRow, 128>>>(x, W1, 0, 0); // launch 3 — ncu capture slot
    k_scan2<<<1, 128>>>();              // launch 4
    k_scan3<<<gN, T>>>();               // launch 5
    k_scatter<<<gE, T>>>(ei);           // launch 6

    k_agg<<<gAgg, T>>>(b1);
    k_gemm<<<gRow, 128>>>(x, W2, 1, 1);
    k_agg<<<gAgg, T>>>(b2);
    k_gemm<<<gRow, 128>>>(x, W3, 1, 1);
    k_agg<<<gAgg, T>>>(b3);

    k_pool_head<<<GG, T>>>(batch, Wl, bl, out);
}